// round 1
// baseline (speedup 1.0000x reference)
#include <cuda_runtime.h>
#include <math.h>

#define Tt 3
#define NB 2
#define HH 360
#define WW 640
#define FF 2
#define HF 720
#define WF 1280
#define PLANE (HF*WF)
#define SRC (HH*WW)

// ---------------- device-global scratch (no allocations allowed) ----------------
__device__ float  g_fb[NB*4*PLANE];   // frame_bicubic, planar [n][c][y][x]
__device__ float  g_fu[NB*4*PLANE];   // frame_up (zero-upsample + jitter shift)
__device__ float  g_hw[NB*4*PLANE];   // warped history (CNN input), planar
__device__ float4 g_ha[NB*PLANE];     // persistent history state, packed NHWC
__device__ float  g_h1[NB*64*PLANE];  // conv1 activations
__device__ float  g_h2[NB*64*PLANE];  // conv2 activations

// ---------------- helpers ----------------
__device__ __forceinline__ void cubw(float t, float w[4]) {
    const float a = -0.75f;
    float t2 = t*t, t3 = t2*t;
    w[0] = a*(t3 - 2.0f*t2 + t);
    w[1] = (a + 2.0f)*t3 - (a + 3.0f)*t2 + 1.0f;
    float s = 1.0f - t;
    w[2] = (a + 2.0f)*s*s*s - (a + 3.0f)*s*s + 1.0f;
    float u = 2.0f - t;
    w[3] = a*u*u*u - 5.0f*a*u*u + 8.0f*a*u - 4.0f*a;
}

__device__ __forceinline__ float depth_tx(float d) {
    // near=0.1, far=100: z = near*far/(far - d*(far-near)); (z-near)/(far-near)
    float z = 10.0f / (100.0f - d * 99.9f);
    return (z - 0.1f) * (1.0f / 99.9f);
}

// ---------------- preprocess: frame_bicubic + frame_up ----------------
__global__ void pre_kernel(const float* __restrict__ frame,  // [NB,3,HH,WW]
                           const float* __restrict__ depth,  // [NB,1,HH,WW]
                           const float* __restrict__ jit,    // [NB,2] (x,y)
                           int first)
{
    int idx = blockIdx.x * blockDim.x + threadIdx.x;
    if (idx >= NB*PLANE) return;
    int x = idx % WF;
    int y = (idx / WF) % HF;
    int n = idx / PLANE;

    float jx = jit[n*2 + 0];
    float jy = jit[n*2 + 1];

    // affine_grid translation + grid_sample bicubic coords (align_corners=False)
    float gx = (2.0f*x + 1.0f) / (float)WF - 1.0f + 2.0f*(0.5f - jx) / (float)WW;
    float gy = (2.0f*y + 1.0f) / (float)HF - 1.0f + 2.0f*(0.5f - jy) / (float)HH;
    float ix = ((gx + 1.0f) * (float)WW - 1.0f) * 0.5f;
    float iy = ((gy + 1.0f) * (float)HH - 1.0f) * 0.5f;
    float x0 = floorf(ix), y0 = floorf(iy);
    float wx[4], wy[4];
    cubw(ix - x0, wx);
    cubw(iy - y0, wy);
    int xi[4], yi[4];
    #pragma unroll
    for (int i = 0; i < 4; i++) {
        xi[i] = min(max((int)x0 + i - 1, 0), WW - 1);
        yi[i] = min(max((int)y0 + i - 1, 0), HH - 1);
    }

    const float* fr = frame + n * 3 * SRC;
    const float* dp = depth + n * SRC;
    float a0 = 0.f, a1 = 0.f, a2 = 0.f, a3 = 0.f;
    #pragma unroll
    for (int i = 0; i < 4; i++) {
        int ro = yi[i] * WW;
        #pragma unroll
        for (int j = 0; j < 4; j++) {
            float wgt = wy[i] * wx[j];
            int off = ro + xi[j];
            a0 += wgt * fr[off];
            a1 += wgt * fr[SRC + off];
            a2 += wgt * fr[2*SRC + off];
            a3 += wgt * depth_tx(dp[off]);
        }
    }
    int o = y * WF + x;
    float* fbp = g_fb + n * 4 * PLANE + o;
    fbp[0] = a0; fbp[PLANE] = a1; fbp[2*PLANE] = a2; fbp[3*PLANE] = a3;
    if (first) {
        float* hwp = g_hw + n * 4 * PLANE + o;
        hwp[0] = a0; hwp[PLANE] = a1; hwp[2*PLANE] = a2; hwp[3*PLANE] = a3;
    }

    // frame_up: out[y][x] = up[y-jy][x-jx], nonzero only on the F-grid
    int jxi = (int)floorf(jx * (float)FF);
    int jyi = (int)floorf(jy * (float)FF);
    int ux = x - jxi, uy = y - jyi;
    float u0 = 0.f, u1 = 0.f, u2 = 0.f, u3 = 0.f;
    if (ux >= 0 && uy >= 0 && (ux % FF) == 0 && (uy % FF) == 0) {
        int off = (uy / FF) * WW + (ux / FF);
        u0 = fr[off]; u1 = fr[SRC + off]; u2 = fr[2*SRC + off];
        u3 = depth_tx(dp[off]);
    }
    float* fup = g_fu + n * 4 * PLANE + o;
    fup[0] = u0; fup[PLANE] = u1; fup[2*PLANE] = u2; fup[3*PLANE] = u3;
}

// ---------------- history warp: mv bilinear upsample + bicubic sample ----------------
__global__ void warp_kernel(const float* __restrict__ mv)   // [NB,HH,WW,2]
{
    int idx = blockIdx.x * blockDim.x + threadIdx.x;
    if (idx >= NB*PLANE) return;
    int x = idx % WF;
    int y = (idx / WF) % HF;
    int n = idx / PLANE;

    // bilinear resize coords (align_corners=False, clamped >= 0)
    float cx = fmaxf(((float)x + 0.5f) / (float)FF - 0.5f, 0.0f);
    float cy = fmaxf(((float)y + 0.5f) / (float)FF - 0.5f, 0.0f);
    float fx0 = floorf(cx), fy0 = floorf(cy);
    float tx = cx - fx0, ty = cy - fy0;
    int x0 = min(max((int)fx0, 0), WW - 1);
    int x1 = min((int)fx0 + 1, WW - 1);
    int y0 = min(max((int)fy0, 0), HH - 1);
    int y1 = min((int)fy0 + 1, HH - 1);

    const float* m = mv + (size_t)n * SRC * 2;
    int i00 = (y0 * WW + x0) * 2, i01 = (y0 * WW + x1) * 2;
    int i10 = (y1 * WW + x0) * 2, i11 = (y1 * WW + x1) * 2;
    float mvx = (m[i00] * (1.f - tx) + m[i01] * tx) * (1.f - ty)
              + (m[i10] * (1.f - tx) + m[i11] * tx) * ty;
    float mvy = (m[i00+1] * (1.f - tx) + m[i01+1] * tx) * (1.f - ty)
              + (m[i10+1] * (1.f - tx) + m[i11+1] * tx) * ty;

    int o = y * WF + x;
    float* hwp = g_hw + n * 4 * PLANE + o;

    bool oob = (mvx > 1.0f) || (mvx < -1.0f) || (mvy > 1.0f) || (mvy < -1.0f);
    if (oob) {
        const float* fbp = g_fb + n * 4 * PLANE + o;
        hwp[0] = fbp[0]; hwp[PLANE] = fbp[PLANE];
        hwp[2*PLANE] = fbp[2*PLANE]; hwp[3*PLANE] = fbp[3*PLANE];
        return;
    }

    float ixf = ((mvx + 1.0f) * (float)WF - 1.0f) * 0.5f;
    float iyf = ((mvy + 1.0f) * (float)HF - 1.0f) * 0.5f;
    float x0f = floorf(ixf), y0f = floorf(iyf);
    float wx[4], wy[4];
    cubw(ixf - x0f, wx);
    cubw(iyf - y0f, wy);
    int xi[4], yi[4];
    #pragma unroll
    for (int i = 0; i < 4; i++) {
        xi[i] = min(max((int)x0f + i - 1, 0), WF - 1);
        yi[i] = min(max((int)y0f + i - 1, 0), HF - 1);
    }
    const float4* hp = g_ha + n * PLANE;
    float a0 = 0.f, a1 = 0.f, a2 = 0.f, a3 = 0.f;
    #pragma unroll
    for (int i = 0; i < 4; i++) {
        int ro = yi[i] * WF;
        #pragma unroll
        for (int j = 0; j < 4; j++) {
            float wgt = wy[i] * wx[j];
            float4 v = hp[ro + xi[j]];
            a0 += wgt * v.x; a1 += wgt * v.y; a2 += wgt * v.z; a3 += wgt * v.w;
        }
    }
    hwp[0] = a0; hwp[PLANE] = a1; hwp[2*PLANE] = a2; hwp[3*PLANE] = a3;
}

// ---------------- conv1: 8 -> 64, ReLU ----------------
__global__ void __launch_bounds__(256) conv1_kernel(const float* __restrict__ w,
                                                    const float* __restrict__ b)
{
    __shared__ float  s_in[8][18][18];
    __shared__ float4 s_w[8*9*16];
    int tid = threadIdx.y * 16 + threadIdx.x;
    int n = blockIdx.z;
    int tx0 = blockIdx.x * 16, ty0 = blockIdx.y * 16;

    float* sw = (float*)s_w;
    for (int i = tid; i < 8*9*64; i += 256) {
        int oc = i & 63, r = i >> 6;
        int ic = r / 9, k = r - ic * 9;
        sw[i] = w[(oc * 8 + ic) * 9 + k];
    }
    for (int i = tid; i < 8*18*18; i += 256) {
        int c = i / 324, rr = i - c * 324;
        int r = rr / 18, cc = rr - r * 18;
        int yy = min(max(ty0 - 1 + r, 0), HF - 1);
        int xx = min(max(tx0 - 1 + cc, 0), WF - 1);
        const float* src = (c < 4) ? (g_fu + (n*4 + c) * PLANE)
                                   : (g_hw + (n*4 + c - 4) * PLANE);
        s_in[c][r][cc] = src[yy * WF + xx];
    }
    __syncthreads();

    float acc[64];
    #pragma unroll
    for (int oc = 0; oc < 64; oc++) acc[oc] = __ldg(&b[oc]);

    for (int c = 0; c < 8; c++) {
        #pragma unroll
        for (int ky = 0; ky < 3; ky++) {
            #pragma unroll
            for (int kx = 0; kx < 3; kx++) {
                float v = s_in[c][threadIdx.y + ky][threadIdx.x + kx];
                const float4* wp = &s_w[(c*9 + ky*3 + kx) * 16];
                #pragma unroll
                for (int q = 0; q < 16; q++) {
                    float4 w4 = wp[q];
                    acc[4*q+0] = fmaf(v, w4.x, acc[4*q+0]);
                    acc[4*q+1] = fmaf(v, w4.y, acc[4*q+1]);
                    acc[4*q+2] = fmaf(v, w4.z, acc[4*q+2]);
                    acc[4*q+3] = fmaf(v, w4.w, acc[4*q+3]);
                }
            }
        }
    }
    int o = (ty0 + threadIdx.y) * WF + (tx0 + threadIdx.x);
    float* dst = g_h1 + n * 64 * PLANE + o;
    #pragma unroll
    for (int oc = 0; oc < 64; oc++) dst[oc * PLANE] = fmaxf(acc[oc], 0.0f);
}

// ---------------- conv2: 64 -> 64, ReLU (ic chunked by 8) ----------------
__global__ void __launch_bounds__(256) conv2_kernel(const float* __restrict__ w,
                                                    const float* __restrict__ b)
{
    __shared__ float  s_in[8][18][18];
    __shared__ float4 s_w[8*9*16];
    int tid = threadIdx.y * 16 + threadIdx.x;
    int n = blockIdx.z;
    int tx0 = blockIdx.x * 16, ty0 = blockIdx.y * 16;

    float acc[64];
    #pragma unroll
    for (int oc = 0; oc < 64; oc++) acc[oc] = __ldg(&b[oc]);

    float* sw = (float*)s_w;
    for (int ck = 0; ck < 8; ck++) {
        __syncthreads();
        for (int i = tid; i < 8*9*64; i += 256) {
            int oc = i & 63, r = i >> 6;
            int ic = r / 9, k = r - ic * 9;
            sw[i] = w[(oc * 64 + ck * 8 + ic) * 9 + k];
        }
        for (int i = tid; i < 8*18*18; i += 256) {
            int c = i / 324, rr = i - c * 324;
            int r = rr / 18, cc = rr - r * 18;
            int yy = min(max(ty0 - 1 + r, 0), HF - 1);
            int xx = min(max(tx0 - 1 + cc, 0), WF - 1);
            s_in[c][r][cc] = g_h1[(n * 64 + ck * 8 + c) * PLANE + yy * WF + xx];
        }
        __syncthreads();

        for (int c = 0; c < 8; c++) {
            #pragma unroll
            for (int ky = 0; ky < 3; ky++) {
                #pragma unroll
                for (int kx = 0; kx < 3; kx++) {
                    float v = s_in[c][threadIdx.y + ky][threadIdx.x + kx];
                    const float4* wp = &s_w[(c*9 + ky*3 + kx) * 16];
                    #pragma unroll
                    for (int q = 0; q < 16; q++) {
                        float4 w4 = wp[q];
                        acc[4*q+0] = fmaf(v, w4.x, acc[4*q+0]);
                        acc[4*q+1] = fmaf(v, w4.y, acc[4*q+1]);
                        acc[4*q+2] = fmaf(v, w4.z, acc[4*q+2]);
                        acc[4*q+3] = fmaf(v, w4.w, acc[4*q+3]);
                    }
                }
            }
        }
    }
    int o = (ty0 + threadIdx.y) * WF + (tx0 + threadIdx.x);
    float* dst = g_h2 + n * 64 * PLANE + o;
    #pragma unroll
    for (int oc = 0; oc < 64; oc++) dst[oc * PLANE] = fmaxf(acc[oc], 0.0f);
}

// ---------------- conv3 (64->2) fused with blend/clamp/output epilogue ----------------
__global__ void __launch_bounds__(256) conv3ep_kernel(const float* __restrict__ w,
                                                      const float* __restrict__ b,
                                                      float* __restrict__ out, int t)
{
    __shared__ float s_in[8][18][18];
    __shared__ float s_w[8*9*2];
    int tid = threadIdx.y * 16 + threadIdx.x;
    int n = blockIdx.z;
    int tx0 = blockIdx.x * 16, ty0 = blockIdx.y * 16;

    float r0 = __ldg(&b[0]);
    float r1 = __ldg(&b[1]);

    for (int ck = 0; ck < 8; ck++) {
        __syncthreads();
        for (int i = tid; i < 8*9*2; i += 256) {
            int oc = i & 1, r = i >> 1;
            int ic = r / 9, k = r - ic * 9;
            s_w[i] = w[(oc * 64 + ck * 8 + ic) * 9 + k];
        }
        for (int i = tid; i < 8*18*18; i += 256) {
            int c = i / 324, rr = i - c * 324;
            int r = rr / 18, cc = rr - r * 18;
            int yy = min(max(ty0 - 1 + r, 0), HF - 1);
            int xx = min(max(tx0 - 1 + cc, 0), WF - 1);
            s_in[c][r][cc] = g_h2[(n * 64 + ck * 8 + c) * PLANE + yy * WF + xx];
        }
        __syncthreads();

        for (int c = 0; c < 8; c++) {
            #pragma unroll
            for (int ky = 0; ky < 3; ky++) {
                #pragma unroll
                for (int kx = 0; kx < 3; kx++) {
                    float v = s_in[c][threadIdx.y + ky][threadIdx.x + kx];
                    int wi = (c*9 + ky*3 + kx) * 2;
                    r0 = fmaf(v, s_w[wi + 0], r0);
                    r1 = fmaf(v, s_w[wi + 1], r1);
                }
            }
        }
    }

    int o = (ty0 + threadIdx.y) * WF + (tx0 + threadIdx.x);
    float alpha = fminf(fmaxf(r0, 0.0f), 1.0f);

    const float* hwp = g_hw + n * 4 * PLANE + o;
    const float* fbp = g_fb + n * 4 * PLANE + o;
    float h0 = hwp[0], h1v = hwp[PLANE], h2v = hwp[2*PLANE], h3v = hwp[3*PLANE];
    float f0 = fbp[0], f1v = fbp[PLANE], f2v = fbp[2*PLANE], f3v = fbp[3*PLANE];
    float ia = 1.0f - alpha;
    float n0 = h0 * ia + f0 * alpha;
    float n1 = h1v * ia + f1v * alpha;
    float n2 = h2v * ia + f2v * alpha;
    float n3 = h3v * ia + f3v * alpha + r1;
    n0 = fminf(fmaxf(n0, 0.0f), 1.0f);
    n1 = fminf(fmaxf(n1, 0.0f), 1.0f);
    n2 = fminf(fmaxf(n2, 0.0f), 1.0f);
    n3 = fminf(fmaxf(n3, 0.0f), 1.0f);

    g_ha[n * PLANE + o] = make_float4(n0, n1, n2, n3);
    float* op = out + ((size_t)(t * NB + n) * 3) * PLANE + o;
    op[0] = n0; op[PLANE] = n1; op[2*PLANE] = n2;
}

// ---------------- launch ----------------
extern "C" void kernel_launch(void* const* d_in, const int* in_sizes, int n_in,
                              void* d_out, int out_size)
{
    const float* frames = (const float*)d_in[0]; // [T,NB,3,HH,WW]
    const float* depths = (const float*)d_in[1]; // [T,NB,1,HH,WW]
    const float* mvs    = (const float*)d_in[2]; // [T,NB,HH,WW,2]
    const float* jits   = (const float*)d_in[3]; // [T,NB,2]
    const float* w1 = (const float*)d_in[4];
    const float* b1 = (const float*)d_in[5];
    const float* w2 = (const float*)d_in[6];
    const float* b2 = (const float*)d_in[7];
    const float* w3 = (const float*)d_in[8];
    const float* b3 = (const float*)d_in[9];
    float* out = (float*)d_out;

    dim3 cgrid(WF/16, HF/16, NB);
    dim3 cblk(16, 16);
    int pgrid = (NB*PLANE + 255) / 256;

    for (int s = 0; s < Tt; s++) {
        int t = Tt - 1 - s;   // reference processes t = T-1 .. 0
        pre_kernel<<<pgrid, 256>>>(frames + (size_t)t * NB * 3 * SRC,
                                   depths + (size_t)t * NB * SRC,
                                   jits + (size_t)t * NB * 2,
                                   (s == 0) ? 1 : 0);
        if (s > 0)
            warp_kernel<<<pgrid, 256>>>(mvs + (size_t)t * NB * SRC * 2);
        conv1_kernel<<<cgrid, cblk>>>(w1, b1);
        conv2_kernel<<<cgrid, cblk>>>(w2, b2);
        conv3ep_kernel<<<cgrid, cblk>>>(w3, b3, out, t);
    }
}

// round 3
// speedup vs baseline: 2.7681x; 2.7681x over previous
#include <cuda_runtime.h>
#include <math.h>
#include <stdint.h>

#define Tt 3
#define NB 2
#define HH 360
#define WW 640
#define FF 2
#define HF 720
#define WF 1280
#define PLANE (HF*WF)
#define SRC (HH*WW)

// ---------------- device-global scratch ----------------
__device__ float4 g_fb4[NB*PLANE];       // frame_bicubic, NHWC float4 (fp32)
__device__ float4 g_hw4[NB*PLANE];       // warped history, NHWC float4 (fp32)
__device__ float4 g_ha [NB*PLANE];       // persistent history state
__device__ float  g_x0 [NB*PLANE*8];     // CNN input, NHWC 8ch (tf32-rounded)
__device__ float  g_h1 [(size_t)NB*PLANE*64]; // conv1 out, NHWC (tf32-rounded)
__device__ float  g_h2 [(size_t)NB*PLANE*64]; // conv2 out, NHWC (fp32)
__device__ float  g_w1p[9*8*64];         // [tap][ic][oc] tf32
__device__ float  g_w2p[9*64*64];        // [tap][ic][oc] tf32
__device__ float  g_w3p[9*2*64];         // [tap][oc][ic] fp32

// ---------------- helpers ----------------
__device__ __forceinline__ float to_tf32(float x) {
    uint32_t u;
    asm("cvt.rna.tf32.f32 %0, %1;" : "=r"(u) : "f"(x));
    return __uint_as_float(u);
}

__device__ __forceinline__ void cubw(float t, float w[4]) {
    const float a = -0.75f;
    float t2 = t*t, t3 = t2*t;
    w[0] = a*(t3 - 2.0f*t2 + t);
    w[1] = (a + 2.0f)*t3 - (a + 3.0f)*t2 + 1.0f;
    float s = 1.0f - t;
    w[2] = (a + 2.0f)*s*s*s - (a + 3.0f)*s*s + 1.0f;
    float u = 2.0f - t;
    w[3] = a*u*u*u - 5.0f*a*u*u + 8.0f*a*u - 4.0f*a;
}

__device__ __forceinline__ float depth_tx(float d) {
    float z = 10.0f / (100.0f - d * 99.9f);
    return (z - 0.1f) * (1.0f / 99.9f);
}

__device__ __forceinline__ void mma_tf32(float c[4], uint32_t a0, uint32_t a1,
                                         uint32_t a2, uint32_t a3,
                                         uint32_t b0, uint32_t b1) {
    asm volatile(
        "mma.sync.aligned.m16n8k8.row.col.f32.tf32.tf32.f32 "
        "{%0,%1,%2,%3}, {%4,%5,%6,%7}, {%8,%9}, {%0,%1,%2,%3};\n"
        : "+f"(c[0]), "+f"(c[1]), "+f"(c[2]), "+f"(c[3])
        : "r"(a0), "r"(a1), "r"(a2), "r"(a3), "r"(b0), "r"(b1));
}

// ---------------- weight prepack (tf32 rounding, [tap][ic][oc]) ----------------
__global__ void prepack_kernel(const float* __restrict__ w1,
                               const float* __restrict__ w2,
                               const float* __restrict__ w3)
{
    int i = blockIdx.x * 256 + threadIdx.x;
    if (i < 9*8*64) {
        int tap = i / 512, rem = i % 512;
        int ic = rem >> 6, oc = rem & 63;
        g_w1p[i] = to_tf32(w1[(oc*8 + ic)*9 + tap]);
    }
    if (i < 9*64*64) {
        int tap = i >> 12, rem = i & 4095;
        int ic = rem >> 6, oc = rem & 63;
        g_w2p[i] = to_tf32(w2[(oc*64 + ic)*9 + tap]);
    }
    if (i < 9*2*64) {
        int tap = i >> 7, rem = i & 127;
        int oc = rem >> 6, ic = rem & 63;
        g_w3p[i] = w3[(oc*64 + ic)*9 + tap];
    }
}

// ---------------- preprocess: frame_bicubic + frame_up ----------------
__global__ void pre_kernel(const float* __restrict__ frame,
                           const float* __restrict__ depth,
                           const float* __restrict__ jit,
                           int first)
{
    int idx = blockIdx.x * blockDim.x + threadIdx.x;
    if (idx >= NB*PLANE) return;
    int x = idx % WF;
    int y = (idx / WF) % HF;
    int n = idx / PLANE;

    float jx = jit[n*2 + 0];
    float jy = jit[n*2 + 1];

    float gx = (2.0f*x + 1.0f) / (float)WF - 1.0f + 2.0f*(0.5f - jx) / (float)WW;
    float gy = (2.0f*y + 1.0f) / (float)HF - 1.0f + 2.0f*(0.5f - jy) / (float)HH;
    float ix = ((gx + 1.0f) * (float)WW - 1.0f) * 0.5f;
    float iy = ((gy + 1.0f) * (float)HH - 1.0f) * 0.5f;
    float x0 = floorf(ix), y0 = floorf(iy);
    float wx[4], wy[4];
    cubw(ix - x0, wx);
    cubw(iy - y0, wy);
    int xi[4], yi[4];
    #pragma unroll
    for (int i = 0; i < 4; i++) {
        xi[i] = min(max((int)x0 + i - 1, 0), WW - 1);
        yi[i] = min(max((int)y0 + i - 1, 0), HH - 1);
    }

    const float* fr = frame + n * 3 * SRC;
    const float* dp = depth + n * SRC;
    float a0 = 0.f, a1 = 0.f, a2 = 0.f, a3 = 0.f;
    #pragma unroll
    for (int i = 0; i < 4; i++) {
        int ro = yi[i] * WW;
        #pragma unroll
        for (int j = 0; j < 4; j++) {
            float wgt = wy[i] * wx[j];
            int off = ro + xi[j];
            a0 += wgt * fr[off];
            a1 += wgt * fr[SRC + off];
            a2 += wgt * fr[2*SRC + off];
            a3 += wgt * depth_tx(dp[off]);
        }
    }
    int o = y * WF + x;
    g_fb4[n * PLANE + o] = make_float4(a0, a1, a2, a3);

    // frame_up
    int jxi = (int)floorf(jx * (float)FF);
    int jyi = (int)floorf(jy * (float)FF);
    int ux = x - jxi, uy = y - jyi;
    float u0 = 0.f, u1 = 0.f, u2 = 0.f, u3 = 0.f;
    if (ux >= 0 && uy >= 0 && (ux % FF) == 0 && (uy % FF) == 0) {
        int off = (uy / FF) * WW + (ux / FF);
        u0 = fr[off]; u1 = fr[SRC + off]; u2 = fr[2*SRC + off];
        u3 = depth_tx(dp[off]);
    }
    float* x0p = g_x0 + ((size_t)n * PLANE + o) * 8;
    x0p[0] = to_tf32(u0); x0p[1] = to_tf32(u1);
    x0p[2] = to_tf32(u2); x0p[3] = to_tf32(u3);
    if (first) {
        g_hw4[n * PLANE + o] = make_float4(a0, a1, a2, a3);
        x0p[4] = to_tf32(a0); x0p[5] = to_tf32(a1);
        x0p[6] = to_tf32(a2); x0p[7] = to_tf32(a3);
    }
}

// ---------------- history warp ----------------
__global__ void warp_kernel(const float* __restrict__ mv)
{
    int idx = blockIdx.x * blockDim.x + threadIdx.x;
    if (idx >= NB*PLANE) return;
    int x = idx % WF;
    int y = (idx / WF) % HF;
    int n = idx / PLANE;

    float cx = fmaxf(((float)x + 0.5f) / (float)FF - 0.5f, 0.0f);
    float cy = fmaxf(((float)y + 0.5f) / (float)FF - 0.5f, 0.0f);
    float fx0 = floorf(cx), fy0 = floorf(cy);
    float tx = cx - fx0, ty = cy - fy0;
    int x0 = min(max((int)fx0, 0), WW - 1);
    int x1 = min((int)fx0 + 1, WW - 1);
    int y0 = min(max((int)fy0, 0), HH - 1);
    int y1 = min((int)fy0 + 1, HH - 1);

    const float* m = mv + (size_t)n * SRC * 2;
    int i00 = (y0 * WW + x0) * 2, i01 = (y0 * WW + x1) * 2;
    int i10 = (y1 * WW + x0) * 2, i11 = (y1 * WW + x1) * 2;
    float mvx = (m[i00] * (1.f - tx) + m[i01] * tx) * (1.f - ty)
              + (m[i10] * (1.f - tx) + m[i11] * tx) * ty;
    float mvy = (m[i00+1] * (1.f - tx) + m[i01+1] * tx) * (1.f - ty)
              + (m[i10+1] * (1.f - tx) + m[i11+1] * tx) * ty;

    int o = y * WF + x;
    float4 res;
    bool oob = (mvx > 1.0f) || (mvx < -1.0f) || (mvy > 1.0f) || (mvy < -1.0f);
    if (oob) {
        res = g_fb4[n * PLANE + o];
    } else {
        float ixf = ((mvx + 1.0f) * (float)WF - 1.0f) * 0.5f;
        float iyf = ((mvy + 1.0f) * (float)HF - 1.0f) * 0.5f;
        float x0f = floorf(ixf), y0f = floorf(iyf);
        float wx[4], wy[4];
        cubw(ixf - x0f, wx);
        cubw(iyf - y0f, wy);
        int xi[4], yi[4];
        #pragma unroll
        for (int i = 0; i < 4; i++) {
            xi[i] = min(max((int)x0f + i - 1, 0), WF - 1);
            yi[i] = min(max((int)y0f + i - 1, 0), HF - 1);
        }
        const float4* hp = g_ha + n * PLANE;
        float a0 = 0.f, a1 = 0.f, a2 = 0.f, a3 = 0.f;
        #pragma unroll
        for (int i = 0; i < 4; i++) {
            int ro = yi[i] * WF;
            #pragma unroll
            for (int j = 0; j < 4; j++) {
                float wgt = wy[i] * wx[j];
                float4 v = hp[ro + xi[j]];
                a0 += wgt * v.x; a1 += wgt * v.y; a2 += wgt * v.z; a3 += wgt * v.w;
            }
        }
        res = make_float4(a0, a1, a2, a3);
    }
    g_hw4[n * PLANE + o] = res;
    float* x0p = g_x0 + ((size_t)n * PLANE + o) * 8;
    x0p[4] = to_tf32(res.x); x0p[5] = to_tf32(res.y);
    x0p[6] = to_tf32(res.z); x0p[7] = to_tf32(res.w);
}

// ================= conv1: 8 -> 64, ReLU, tf32 MMA =================
// tile: 32x(x) * 4y = 128 px, block 256 thr = 8 warps (2 oc-halves x 4 rows)
__global__ void __launch_bounds__(256, 2) conv1_kernel(const float* __restrict__ bias)
{
    __shared__ float s_in[204*12];   // [6 rows][34 cols][8ch pad 12]
    __shared__ float s_w [72*72];    // [k=tap*8+ic][oc pad 72]

    const int tid = threadIdx.x;
    const int lane = tid & 31, wid = tid >> 5;
    const int warp_m = wid & 1, ly = wid >> 1;
    const int gid = lane >> 2, tig = lane & 3;
    const int n = blockIdx.z;
    const int x0 = blockIdx.x * 32, y0 = blockIdx.y * 4;

    for (int i = tid; i < 9*8*64; i += 256) {
        int k = i >> 6, oc = i & 63;
        s_w[k*72 + oc] = g_w1p[i];
    }
    for (int i = tid; i < 204; i += 256) {
        int r = i / 34, c = i - r * 34;
        int gy = min(max(y0 - 1 + r, 0), HF - 1);
        int gx = min(max(x0 - 1 + c, 0), WF - 1);
        const float4* src = (const float4*)(g_x0 + ((size_t)n * PLANE + gy * WF + gx) * 8);
        float4* dst = (float4*)(s_in + i * 12);
        dst[0] = src[0]; dst[1] = src[1];
    }
    __syncthreads();

    float acc[2][4][4] = {};
    const int m0 = warp_m * 32;

    #pragma unroll
    for (int tap = 0; tap < 9; tap++) {
        int dy = tap / 3, dx = tap - dy * 3;
        uint32_t A[2][4];
        #pragma unroll
        for (int mt = 0; mt < 2; mt++) {
            const float* wp = s_w + (tap*8 + tig) * 72 + m0 + mt*16 + gid;
            A[mt][0] = __float_as_uint(wp[0]);
            A[mt][1] = __float_as_uint(wp[8]);
            A[mt][2] = __float_as_uint(wp[4*72]);
            A[mt][3] = __float_as_uint(wp[4*72 + 8]);
        }
        const float* binb = s_in + ((ly + dy) * 34 + dx + gid) * 12 + tig;
        #pragma unroll
        for (int nt = 0; nt < 4; nt++) {
            const float* bp = binb + nt * 8 * 12;
            uint32_t B0 = __float_as_uint(bp[0]);
            uint32_t B1 = __float_as_uint(bp[4]);
            mma_tf32(acc[0][nt], A[0][0], A[0][1], A[0][2], A[0][3], B0, B1);
            mma_tf32(acc[1][nt], A[1][0], A[1][1], A[1][2], A[1][3], B0, B1);
        }
    }

    float* dst = g_h1 + ((size_t)n * PLANE + (y0 + ly) * WF + x0) * 64;
    #pragma unroll
    for (int mt = 0; mt < 2; mt++) {
        int oc0 = m0 + mt*16 + gid, oc1 = oc0 + 8;
        float bv0 = __ldg(&bias[oc0]), bv1 = __ldg(&bias[oc1]);
        #pragma unroll
        for (int nt = 0; nt < 4; nt++) {
            int px = nt*8 + 2*tig;
            dst[(size_t)px*64 + oc0]     = to_tf32(fmaxf(acc[mt][nt][0] + bv0, 0.f));
            dst[(size_t)(px+1)*64 + oc0] = to_tf32(fmaxf(acc[mt][nt][1] + bv0, 0.f));
            dst[(size_t)px*64 + oc1]     = to_tf32(fmaxf(acc[mt][nt][2] + bv1, 0.f));
            dst[(size_t)(px+1)*64 + oc1] = to_tf32(fmaxf(acc[mt][nt][3] + bv1, 0.f));
        }
    }
}

// ================= conv2: 64 -> 64, ReLU, tf32 MMA =================
#define C2_SIN (204*68)
#define C2_SW  (64*72)
#define C2_SMEM ((C2_SIN + C2_SW) * 4)

__global__ void __launch_bounds__(256, 2) conv2_kernel(const float* __restrict__ bias)
{
    extern __shared__ float sm[];
    float* s_in = sm;              // [6][34][64 pad 68]
    float* s_w  = sm + C2_SIN;     // [64][oc pad 72]

    const int tid = threadIdx.x;
    const int lane = tid & 31, wid = tid >> 5;
    const int warp_m = wid & 1, ly = wid >> 1;
    const int gid = lane >> 2, tig = lane & 3;
    const int n = blockIdx.z;
    const int x0 = blockIdx.x * 32, y0 = blockIdx.y * 4;

    for (int i = tid; i < 204; i += 256) {
        int r = i / 34, c = i - r * 34;
        int gy = min(max(y0 - 1 + r, 0), HF - 1);
        int gx = min(max(x0 - 1 + c, 0), WF - 1);
        const float4* src = (const float4*)(g_h1 + ((size_t)n * PLANE + gy * WF + gx) * 64);
        float4* dst = (float4*)(s_in + i * 68);
        #pragma unroll
        for (int j = 0; j < 16; j++) dst[j] = src[j];
    }

    float acc[2][4][4] = {};
    const int m0 = warp_m * 32;

    for (int tap = 0; tap < 9; tap++) {
        __syncthreads();
        for (int i = tid; i < 4096; i += 256) {
            int k = i >> 6, oc = i & 63;
            s_w[k*72 + oc] = g_w2p[tap*4096 + i];
        }
        __syncthreads();
        int dy = tap / 3, dx = tap - dy * 3;
        const float* binb = s_in + ((ly + dy) * 34 + dx + gid) * 68;
        #pragma unroll
        for (int kt = 0; kt < 8; kt++) {
            int kb = kt * 8;
            uint32_t A[2][4];
            #pragma unroll
            for (int mt = 0; mt < 2; mt++) {
                const float* wp = s_w + (kb + tig) * 72 + m0 + mt*16 + gid;
                A[mt][0] = __float_as_uint(wp[0]);
                A[mt][1] = __float_as_uint(wp[8]);
                A[mt][2] = __float_as_uint(wp[4*72]);
                A[mt][3] = __float_as_uint(wp[4*72 + 8]);
            }
            #pragma unroll
            for (int nt = 0; nt < 4; nt++) {
                const float* bp = binb + nt * 8 * 68 + kb + tig;
                uint32_t B0 = __float_as_uint(bp[0]);
                uint32_t B1 = __float_as_uint(bp[4]);
                mma_tf32(acc[0][nt], A[0][0], A[0][1], A[0][2], A[0][3], B0, B1);
                mma_tf32(acc[1][nt], A[1][0], A[1][1], A[1][2], A[1][3], B0, B1);
            }
        }
    }

    float* dst = g_h2 + ((size_t)n * PLANE + (y0 + ly) * WF + x0) * 64;
    #pragma unroll
    for (int mt = 0; mt < 2; mt++) {
        int oc0 = m0 + mt*16 + gid, oc1 = oc0 + 8;
        float bv0 = __ldg(&bias[oc0]), bv1 = __ldg(&bias[oc1]);
        #pragma unroll
        for (int nt = 0; nt < 4; nt++) {
            int px = nt*8 + 2*tig;
            dst[(size_t)px*64 + oc0]     = fmaxf(acc[mt][nt][0] + bv0, 0.f);
            dst[(size_t)(px+1)*64 + oc0] = fmaxf(acc[mt][nt][1] + bv0, 0.f);
            dst[(size_t)px*64 + oc1]     = fmaxf(acc[mt][nt][2] + bv1, 0.f);
            dst[(size_t)(px+1)*64 + oc1] = fmaxf(acc[mt][nt][3] + bv1, 0.f);
        }
    }
}

// ================= conv3 (64->2) + blend/clamp epilogue =================
__global__ void __launch_bounds__(256) conv3ep_kernel(const float* __restrict__ bias,
                                                      float* __restrict__ out, int t)
{
    __shared__ float s_w3[9*2*64];  // [tap][oc][ic]
    for (int i = threadIdx.x; i < 9*2*64; i += 256) s_w3[i] = g_w3p[i];
    __syncthreads();

    int idx = blockIdx.x * 256 + threadIdx.x;
    if (idx >= NB*PLANE) return;
    int x = idx % WF;
    int y = (idx / WF) % HF;
    int n = idx / PLANE;

    float r0 = __ldg(&bias[0]);
    float r1 = __ldg(&bias[1]);

    #pragma unroll
    for (int tap = 0; tap < 9; tap++) {
        int dy = tap / 3, dx = tap - dy * 3;
        int gy = min(max(y + dy - 1, 0), HF - 1);
        int gx = min(max(x + dx - 1, 0), WF - 1);
        const float4* p = (const float4*)(g_h2 + ((size_t)n * PLANE + gy * WF + gx) * 64);
        const float4* w0 = (const float4*)(s_w3 + tap * 128);
        const float4* w1 = (const float4*)(s_w3 + tap * 128 + 64);
        #pragma unroll
        for (int j = 0; j < 16; j++) {
            float4 v = p[j];
            float4 a = w0[j], b = w1[j];
            r0 += v.x*a.x + v.y*a.y + v.z*a.z + v.w*a.w;
            r1 += v.x*b.x + v.y*b.y + v.z*b.z + v.w*b.w;
        }
    }

    int o = y * WF + x;
    float alpha = fminf(fmaxf(r0, 0.0f), 1.0f);
    float4 h = g_hw4[n * PLANE + o];
    float4 f = g_fb4[n * PLANE + o];
    float ia = 1.0f - alpha;
    float n0 = fminf(fmaxf(h.x * ia + f.x * alpha, 0.f), 1.f);
    float n1 = fminf(fmaxf(h.y * ia + f.y * alpha, 0.f), 1.f);
    float n2 = fminf(fmaxf(h.z * ia + f.z * alpha, 0.f), 1.f);
    float n3 = fminf(fmaxf(h.w * ia + f.w * alpha + r1, 0.f), 1.f);

    g_ha[n * PLANE + o] = make_float4(n0, n1, n2, n3);
    float* op = out + ((size_t)(t * NB + n) * 3) * PLANE + o;
    op[0] = n0; op[PLANE] = n1; op[2*PLANE] = n2;
}

// ---------------- launch ----------------
extern "C" void kernel_launch(void* const* d_in, const int* in_sizes, int n_in,
                              void* d_out, int out_size)
{
    const float* frames = (const float*)d_in[0];
    const float* depths = (const float*)d_in[1];
    const float* mvs    = (const float*)d_in[2];
    const float* jits   = (const float*)d_in[3];
    const float* w1 = (const float*)d_in[4];
    const float* b1 = (const float*)d_in[5];
    const float* w2 = (const float*)d_in[6];
    const float* b2 = (const float*)d_in[7];
    const float* w3 = (const float*)d_in[8];
    const float* b3 = (const float*)d_in[9];
    float* out = (float*)d_out;

    cudaFuncSetAttribute(conv2_kernel, cudaFuncAttributeMaxDynamicSharedMemorySize, C2_SMEM);

    dim3 cgrid(WF/32, HF/4, NB);
    int pgrid = (NB*PLANE + 255) / 256;

    prepack_kernel<<<144, 256>>>(w1, w2, w3);

    for (int s = 0; s < Tt; s++) {
        int t = Tt - 1 - s;
        pre_kernel<<<pgrid, 256>>>(frames + (size_t)t * NB * 3 * SRC,
                                   depths + (size_t)t * NB * SRC,
                                   jits + (size_t)t * NB * 2,
                                   (s == 0) ? 1 : 0);
        if (s > 0)
            warp_kernel<<<pgrid, 256>>>(mvs + (size_t)t * NB * SRC * 2);
        conv1_kernel<<<cgrid, 256>>>(b1);
        conv2_kernel<<<cgrid, 256, C2_SMEM>>>(b2);
        conv3ep_kernel<<<pgrid, 256>>>(b3, out, t);
    }
}

// round 5
// speedup vs baseline: 7.2008x; 2.6014x over previous
#include <cuda_runtime.h>
#include <cuda_bf16.h>
#include <math.h>
#include <stdint.h>

#define Tt 3
#define NB 2
#define HH 360
#define WW 640
#define FF 2
#define HF 720
#define WF 1280
#define PLANE (HF*WF)
#define SRC (HH*WW)

// ---------------- device-global scratch ----------------
__device__ float4 g_fb4[NB*PLANE];            // frame_bicubic, NHWC float4 (fp32)
__device__ float4 g_hw4[NB*PLANE];            // warped history, NHWC float4 (fp32)
__device__ float4 g_ha [NB*PLANE];            // persistent history state
__device__ __nv_bfloat16 g_x0[(size_t)NB*PLANE*8];   // CNN input NHWC bf16
__device__ __nv_bfloat16 g_h1[(size_t)NB*PLANE*64];  // conv1 out NHWC bf16
__device__ __nv_bfloat16 g_h2[(size_t)NB*PLANE*64];  // conv2 out NHWC bf16
__device__ uint4 g_w1f[5*2*2*32];             // conv1 A fragments [kc][wm][mt][lane]
__device__ uint4 g_w2f[9*4*2*2*32];           // conv2 A fragments [tap][kt][wm][mt][lane]
__device__ float g_w3p[9*2*64];               // conv3 weights [tap][oc][ic] fp32

// ---------------- helpers ----------------
__device__ __forceinline__ void cubw(float t, float w[4]) {
    const float a = -0.75f;
    float t2 = t*t, t3 = t2*t;
    w[0] = a*(t3 - 2.0f*t2 + t);
    w[1] = (a + 2.0f)*t3 - (a + 3.0f)*t2 + 1.0f;
    float s = 1.0f - t;
    w[2] = (a + 2.0f)*s*s*s - (a + 3.0f)*s*s + 1.0f;
    float u = 2.0f - t;
    w[3] = a*u*u*u - 5.0f*a*u*u + 8.0f*a*u - 4.0f*a;
}

__device__ __forceinline__ float depth_tx(float d) {
    float z = 10.0f / (100.0f - d * 99.9f);
    return (z - 0.1f) * (1.0f / 99.9f);
}

__device__ __forceinline__ uint32_t packbf(float lo, float hi) {
    __nv_bfloat162 h = __floats2bfloat162_rn(lo, hi);
    return *reinterpret_cast<uint32_t*>(&h);
}

__device__ __forceinline__ void mma_bf16(float c[4], uint32_t a0, uint32_t a1,
                                         uint32_t a2, uint32_t a3,
                                         uint32_t b0, uint32_t b1) {
    asm volatile(
        "mma.sync.aligned.m16n8k16.row.col.f32.bf16.bf16.f32 "
        "{%0,%1,%2,%3}, {%4,%5,%6,%7}, {%8,%9}, {%0,%1,%2,%3};\n"
        : "+f"(c[0]), "+f"(c[1]), "+f"(c[2]), "+f"(c[3])
        : "r"(a0), "r"(a1), "r"(a2), "r"(a3), "r"(b0), "r"(b1));
}

// ---------------- weight prepack into MMA A-fragment layouts ----------------
__global__ void prepack_kernel(const float* __restrict__ w1,
                               const float* __restrict__ w2,
                               const float* __restrict__ w3)
{
    int i = blockIdx.x * 256 + threadIdx.x;
    if (i < 4608) {
        // conv2: e = (((tap*4+kt)*2+wm)*2+mt)*32 + lane
        int lane = i & 31;
        int mt = (i >> 5) & 1, wm = (i >> 6) & 1;
        int kt = (i >> 7) & 3, tap = i >> 9;
        int gid = lane >> 2, tig = lane & 3;
        int oc = wm*32 + mt*16 + gid;
        int k0 = kt*16 + 2*tig;
        uint4 v;
        v.x = packbf(w2[(oc*64 + k0)*9 + tap],       w2[(oc*64 + k0 + 1)*9 + tap]);
        v.y = packbf(w2[((oc+8)*64 + k0)*9 + tap],   w2[((oc+8)*64 + k0 + 1)*9 + tap]);
        v.z = packbf(w2[(oc*64 + k0 + 8)*9 + tap],   w2[(oc*64 + k0 + 9)*9 + tap]);
        v.w = packbf(w2[((oc+8)*64 + k0 + 8)*9 + tap], w2[((oc+8)*64 + k0 + 9)*9 + tap]);
        g_w2f[i] = v;
    } else if (i < 4608 + 640) {
        // conv1: K = 80 = 5 chunks of (2 taps x 8 ic); tap 9 is zero pad
        int f = i - 4608;
        int lane = f & 31;
        int mt = (f >> 5) & 1, wm = (f >> 6) & 1;
        int kc = f >> 7;
        int gid = lane >> 2, tig = lane & 3;
        int oc = wm*32 + mt*16 + gid;
        int ic = 2*tig;
        int tlo = 2*kc, thi = 2*kc + 1;
        uint4 v;
        v.x = packbf(w1[(oc*8 + ic)*9 + tlo],     w1[(oc*8 + ic + 1)*9 + tlo]);
        v.y = packbf(w1[((oc+8)*8 + ic)*9 + tlo], w1[((oc+8)*8 + ic + 1)*9 + tlo]);
        if (thi <= 8) {
            v.z = packbf(w1[(oc*8 + ic)*9 + thi],     w1[(oc*8 + ic + 1)*9 + thi]);
            v.w = packbf(w1[((oc+8)*8 + ic)*9 + thi], w1[((oc+8)*8 + ic + 1)*9 + thi]);
        } else { v.z = 0u; v.w = 0u; }
        g_w1f[f] = v;
    } else if (i < 4608 + 640 + 1152) {
        int j = i - 5248;
        int tap = j >> 7, rem = j & 127;
        int oc = rem >> 6, ic = rem & 63;
        g_w3p[j] = w3[(oc*64 + ic)*9 + tap];
    }
}

// ---------------- preprocess: frame_bicubic + frame_up ----------------
__global__ void pre_kernel(const float* __restrict__ frame,
                           const float* __restrict__ depth,
                           const float* __restrict__ jit,
                           int first)
{
    int idx = blockIdx.x * blockDim.x + threadIdx.x;
    if (idx >= NB*PLANE) return;
    int x = idx % WF;
    int y = (idx / WF) % HF;
    int n = idx / PLANE;

    float jx = jit[n*2 + 0];
    float jy = jit[n*2 + 1];

    float gx = (2.0f*x + 1.0f) / (float)WF - 1.0f + 2.0f*(0.5f - jx) / (float)WW;
    float gy = (2.0f*y + 1.0f) / (float)HF - 1.0f + 2.0f*(0.5f - jy) / (float)HH;
    float ix = ((gx + 1.0f) * (float)WW - 1.0f) * 0.5f;
    float iy = ((gy + 1.0f) * (float)HH - 1.0f) * 0.5f;
    float x0 = floorf(ix), y0 = floorf(iy);
    float wx[4], wy[4];
    cubw(ix - x0, wx);
    cubw(iy - y0, wy);
    int xi[4], yi[4];
    #pragma unroll
    for (int i = 0; i < 4; i++) {
        xi[i] = min(max((int)x0 + i - 1, 0), WW - 1);
        yi[i] = min(max((int)y0 + i - 1, 0), HH - 1);
    }

    const float* fr = frame + n * 3 * SRC;
    const float* dp = depth + n * SRC;
    float a0 = 0.f, a1 = 0.f, a2 = 0.f, a3 = 0.f;
    #pragma unroll
    for (int i = 0; i < 4; i++) {
        int ro = yi[i] * WW;
        #pragma unroll
        for (int j = 0; j < 4; j++) {
            float wgt = wy[i] * wx[j];
            int off = ro + xi[j];
            a0 += wgt * fr[off];
            a1 += wgt * fr[SRC + off];
            a2 += wgt * fr[2*SRC + off];
            a3 += wgt * depth_tx(dp[off]);
        }
    }
    int o = y * WF + x;
    g_fb4[n * PLANE + o] = make_float4(a0, a1, a2, a3);

    // frame_up
    int jxi = (int)floorf(jx * (float)FF);
    int jyi = (int)floorf(jy * (float)FF);
    int ux = x - jxi, uy = y - jyi;
    float u0 = 0.f, u1 = 0.f, u2 = 0.f, u3 = 0.f;
    if (ux >= 0 && uy >= 0 && (ux % FF) == 0 && (uy % FF) == 0) {
        int off = (uy / FF) * WW + (ux / FF);
        u0 = fr[off]; u1 = fr[SRC + off]; u2 = fr[2*SRC + off];
        u3 = depth_tx(dp[off]);
    }
    __nv_bfloat162* x0p = (__nv_bfloat162*)(g_x0 + ((size_t)n * PLANE + o) * 8);
    x0p[0] = __floats2bfloat162_rn(u0, u1);
    x0p[1] = __floats2bfloat162_rn(u2, u3);
    if (first) {
        g_hw4[n * PLANE + o] = make_float4(a0, a1, a2, a3);
        x0p[2] = __floats2bfloat162_rn(a0, a1);
        x0p[3] = __floats2bfloat162_rn(a2, a3);
    }
}

// ---------------- history warp ----------------
__global__ void warp_kernel(const float* __restrict__ mv)
{
    int idx = blockIdx.x * blockDim.x + threadIdx.x;
    if (idx >= NB*PLANE) return;
    int x = idx % WF;
    int y = (idx / WF) % HF;
    int n = idx / PLANE;

    float cx = fmaxf(((float)x + 0.5f) / (float)FF - 0.5f, 0.0f);
    float cy = fmaxf(((float)y + 0.5f) / (float)FF - 0.5f, 0.0f);
    float fx0 = floorf(cx), fy0 = floorf(cy);
    float tx = cx - fx0, ty = cy - fy0;
    int x0 = min(max((int)fx0, 0), WW - 1);
    int x1 = min((int)fx0 + 1, WW - 1);
    int y0 = min(max((int)fy0, 0), HH - 1);
    int y1 = min((int)fy0 + 1, HH - 1);

    const float* m = mv + (size_t)n * SRC * 2;
    int i00 = (y0 * WW + x0) * 2, i01 = (y0 * WW + x1) * 2;
    int i10 = (y1 * WW + x0) * 2, i11 = (y1 * WW + x1) * 2;
    float mvx = (m[i00] * (1.f - tx) + m[i01] * tx) * (1.f - ty)
              + (m[i10] * (1.f - tx) + m[i11] * tx) * ty;
    float mvy = (m[i00+1] * (1.f - tx) + m[i01+1] * tx) * (1.f - ty)
              + (m[i10+1] * (1.f - tx) + m[i11+1] * tx) * ty;

    int o = y * WF + x;
    float4 res;
    bool oob = (mvx > 1.0f) || (mvx < -1.0f) || (mvy > 1.0f) || (mvy < -1.0f);
    if (oob) {
        res = g_fb4[n * PLANE + o];
    } else {
        float ixf = ((mvx + 1.0f) * (float)WF - 1.0f) * 0.5f;
        float iyf = ((mvy + 1.0f) * (float)HF - 1.0f) * 0.5f;
        float x0f = floorf(ixf), y0f = floorf(iyf);
        float wx[4], wy[4];
        cubw(ixf - x0f, wx);
        cubw(iyf - y0f, wy);
        int xi[4], yi[4];
        #pragma unroll
        for (int i = 0; i < 4; i++) {
            xi[i] = min(max((int)x0f + i - 1, 0), WF - 1);
            yi[i] = min(max((int)y0f + i - 1, 0), HF - 1);
        }
        const float4* hp = g_ha + n * PLANE;
        float a0 = 0.f, a1 = 0.f, a2 = 0.f, a3 = 0.f;
        #pragma unroll
        for (int i = 0; i < 4; i++) {
            int ro = yi[i] * WF;
            #pragma unroll
            for (int j = 0; j < 4; j++) {
                float wgt = wy[i] * wx[j];
                float4 v = hp[ro + xi[j]];
                a0 += wgt * v.x; a1 += wgt * v.y; a2 += wgt * v.z; a3 += wgt * v.w;
            }
        }
        res = make_float4(a0, a1, a2, a3);
    }
    g_hw4[n * PLANE + o] = res;
    __nv_bfloat162* x0p = (__nv_bfloat162*)(g_x0 + ((size_t)n * PLANE + o) * 8);
    x0p[2] = __floats2bfloat162_rn(res.x, res.y);
    x0p[3] = __floats2bfloat162_rn(res.z, res.w);
}

// ================= conv1: 8 -> 64, ReLU, bf16 MMA (K=80 padded) =================
__global__ void __launch_bounds__(256) conv1_kernel(const float* __restrict__ bias)
{
    __shared__ uint4 s_x0[204];   // [6 rows][34 cols] x 8ch bf16 = 16B/px

    const int tid = threadIdx.x;
    const int lane = tid & 31, wid = tid >> 5;
    const int warp_m = wid & 1, ly = wid >> 1;
    const int gid = lane >> 2, tig = lane & 3;
    const int n = blockIdx.z;
    const int x0t = blockIdx.x * 32, y0t = blockIdx.y * 4;

    for (int i = tid; i < 204; i += 256) {
        int r = i / 34, c = i - r * 34;
        int gy = min(max(y0t - 1 + r, 0), HF - 1);
        int gx = min(max(x0t - 1 + c, 0), WF - 1);
        s_x0[i] = *(const uint4*)(g_x0 + ((size_t)n * PLANE + gy * WF + gx) * 8);
    }
    __syncthreads();

    float acc[2][4][4] = {};
    const uint32_t* sp = (const uint32_t*)s_x0;

    #pragma unroll
    for (int kc = 0; kc < 5; kc++) {
        int tlo = 2*kc, thi = 2*kc + 1;
        uint4 A0 = __ldg(&g_w1f[((kc*2 + warp_m)*2 + 0)*32 + lane]);
        uint4 A1 = __ldg(&g_w1f[((kc*2 + warp_m)*2 + 1)*32 + lane]);
        int blo = (ly + tlo/3)*34 + tlo%3 + gid;
        if (thi <= 8) {
            int bhi = (ly + thi/3)*34 + thi%3 + gid;
            #pragma unroll
            for (int nt = 0; nt < 4; nt++) {
                uint32_t b0 = sp[(blo + nt*8)*4 + tig];
                uint32_t b1 = sp[(bhi + nt*8)*4 + tig];
                mma_bf16(acc[0][nt], A0.x, A0.y, A0.z, A0.w, b0, b1);
                mma_bf16(acc[1][nt], A1.x, A1.y, A1.z, A1.w, b0, b1);
            }
        } else {
            #pragma unroll
            for (int nt = 0; nt < 4; nt++) {
                uint32_t b0 = sp[(blo + nt*8)*4 + tig];
                mma_bf16(acc[0][nt], A0.x, A0.y, A0.z, A0.w, b0, 0u);
                mma_bf16(acc[1][nt], A1.x, A1.y, A1.z, A1.w, b0, 0u);
            }
        }
    }

    __nv_bfloat16* dst = g_h1 + ((size_t)n * PLANE + (y0t + ly) * WF + x0t) * 64;
    const int m0 = warp_m * 32;
    #pragma unroll
    for (int mt = 0; mt < 2; mt++) {
        int oc0 = m0 + mt*16 + gid, oc1 = oc0 + 8;
        float bv0 = __ldg(&bias[oc0]), bv1 = __ldg(&bias[oc1]);
        #pragma unroll
        for (int nt = 0; nt < 4; nt++) {
            int px = nt*8 + 2*tig;
            dst[(size_t)px*64 + oc0]     = __float2bfloat16_rn(fmaxf(acc[mt][nt][0] + bv0, 0.f));
            dst[(size_t)(px+1)*64 + oc0] = __float2bfloat16_rn(fmaxf(acc[mt][nt][1] + bv0, 0.f));
            dst[(size_t)px*64 + oc1]     = __float2bfloat16_rn(fmaxf(acc[mt][nt][2] + bv1, 0.f));
            dst[(size_t)(px+1)*64 + oc1] = __float2bfloat16_rn(fmaxf(acc[mt][nt][3] + bv1, 0.f));
        }
    }
}

// ================= conv2: 64 -> 64, ReLU, bf16 MMA =================
__global__ void __launch_bounds__(256) conv2_kernel(const float* __restrict__ bias)
{
    __shared__ uint4 s_in[204*9];  // [px 6x34][64ch bf16 = 8 uint4, pad to 9]

    const int tid = threadIdx.x;
    const int lane = tid & 31, wid = tid >> 5;
    const int warp_m = wid & 1, ly = wid >> 1;
    const int gid = lane >> 2, tig = lane & 3;
    const int n = blockIdx.z;
    const int x0t = blockIdx.x * 32, y0t = blockIdx.y * 4;

    for (int i = tid; i < 204; i += 256) {
        int r = i / 34, c = i - r * 34;
        int gy = min(max(y0t - 1 + r, 0), HF - 1);
        int gx = min(max(x0t - 1 + c, 0), WF - 1);
        const uint4* src = (const uint4*)(g_h1 + ((size_t)n * PLANE + gy * WF + gx) * 64);
        uint4* dst = s_in + i * 9;
        #pragma unroll
        for (int j = 0; j < 8; j++) dst[j] = src[j];
    }
    __syncthreads();

    float acc[2][4][4] = {};
    const uint32_t* s32 = (const uint32_t*)s_in;

    for (int tap = 0; tap < 9; tap++) {
        int prow = (ly + tap/3)*34 + tap%3 + gid;
        #pragma unroll
        for (int kt = 0; kt < 4; kt++) {
            uint4 A0 = __ldg(&g_w2f[((tap*4 + kt)*4 + warp_m*2 + 0)*32 + lane]);
            uint4 A1 = __ldg(&g_w2f[((tap*4 + kt)*4 + warp_m*2 + 1)*32 + lane]);
            #pragma unroll
            for (int nt = 0; nt < 4; nt++) {
                int w = (prow + nt*8)*36 + kt*8 + tig;
                uint32_t b0 = s32[w];
                uint32_t b1 = s32[w + 4];
                mma_bf16(acc[0][nt], A0.x, A0.y, A0.z, A0.w, b0, b1);
                mma_bf16(acc[1][nt], A1.x, A1.y, A1.z, A1.w, b0, b1);
            }
        }
    }

    __nv_bfloat16* dst = g_h2 + ((size_t)n * PLANE + (y0t + ly) * WF + x0t) * 64;
    const int m0 = warp_m * 32;
    #pragma unroll
    for (int mt = 0; mt < 2; mt++) {
        int oc0 = m0 + mt*16 + gid, oc1 = oc0 + 8;
        float bv0 = __ldg(&bias[oc0]), bv1 = __ldg(&bias[oc1]);
        #pragma unroll
        for (int nt = 0; nt < 4; nt++) {
            int px = nt*8 + 2*tig;
            dst[(size_t)px*64 + oc0]     = __float2bfloat16_rn(fmaxf(acc[mt][nt][0] + bv0, 0.f));
            dst[(size_t)(px+1)*64 + oc0] = __float2bfloat16_rn(fmaxf(acc[mt][nt][1] + bv0, 0.f));
            dst[(size_t)px*64 + oc1]     = __float2bfloat16_rn(fmaxf(acc[mt][nt][2] + bv1, 0.f));
            dst[(size_t)(px+1)*64 + oc1] = __float2bfloat16_rn(fmaxf(acc[mt][nt][3] + bv1, 0.f));
        }
    }
}

// ================= conv3 (64->2) + blend/clamp epilogue =================
#define C3_SMEM (324*9*16 + 1152*4)

__global__ void __launch_bounds__(256) conv3ep_kernel(const float* __restrict__ bias,
                                                      float* __restrict__ out, int t)
{
    extern __shared__ char cm[];
    uint4* s_h2 = (uint4*)cm;                       // [18x18 px][8 uint4 pad 9]
    float* s_w3 = (float*)(cm + 324*9*16);          // [tap][oc][ic]

    const int tid = threadIdx.y * 16 + threadIdx.x;
    const int n = blockIdx.z;
    const int x0t = blockIdx.x * 16, y0t = blockIdx.y * 16;

    for (int i = tid; i < 1152; i += 256) s_w3[i] = g_w3p[i];
    for (int i = tid; i < 324; i += 256) {
        int r = i / 18, c = i - r * 18;
        int gy = min(max(y0t - 1 + r, 0), HF - 1);
        int gx = min(max(x0t - 1 + c, 0), WF - 1);
        const uint4* src = (const uint4*)(g_h2 + ((size_t)n * PLANE + gy * WF + gx) * 64);
        uint4* dst = s_h2 + i * 9;
        #pragma unroll
        for (int j = 0; j < 8; j++) dst[j] = src[j];
    }
    __syncthreads();

    float r0 = __ldg(&bias[0]);
    float r1 = __ldg(&bias[1]);

    #pragma unroll
    for (int tap = 0; tap < 9; tap++) {
        int p = (threadIdx.y + tap/3) * 18 + threadIdx.x + tap%3;
        const uint4* pp = s_h2 + p * 9;
        const float* wa = s_w3 + tap * 128;
        const float* wb = wa + 64;
        #pragma unroll
        for (int q = 0; q < 8; q++) {
            uint4 v = pp[q];
            float2 f0 = __bfloat1622float2(*(__nv_bfloat162*)&v.x);
            float2 f1 = __bfloat1622float2(*(__nv_bfloat162*)&v.y);
            float2 f2 = __bfloat1622float2(*(__nv_bfloat162*)&v.z);
            float2 f3 = __bfloat1622float2(*(__nv_bfloat162*)&v.w);
            int k = q * 8;
            r0 += f0.x*wa[k]   + f0.y*wa[k+1] + f1.x*wa[k+2] + f1.y*wa[k+3]
                + f2.x*wa[k+4] + f2.y*wa[k+5] + f3.x*wa[k+6] + f3.y*wa[k+7];
            r1 += f0.x*wb[k]   + f0.y*wb[k+1] + f1.x*wb[k+2] + f1.y*wb[k+3]
                + f2.x*wb[k+4] + f2.y*wb[k+5] + f3.x*wb[k+6] + f3.y*wb[k+7];
        }
    }

    int x = x0t + threadIdx.x;
    int y = y0t + threadIdx.y;
    int o = y * WF + x;
    float alpha = fminf(fmaxf(r0, 0.0f), 1.0f);
    float4 h = g_hw4[n * PLANE + o];
    float4 f = g_fb4[n * PLANE + o];
    float ia = 1.0f - alpha;
    float n0 = fminf(fmaxf(h.x * ia + f.x * alpha, 0.f), 1.f);
    float n1 = fminf(fmaxf(h.y * ia + f.y * alpha, 0.f), 1.f);
    float n2 = fminf(fmaxf(h.z * ia + f.z * alpha, 0.f), 1.f);
    float n3 = fminf(fmaxf(h.w * ia + f.w * alpha + r1, 0.f), 1.f);

    g_ha[n * PLANE + o] = make_float4(n0, n1, n2, n3);
    float* op = out + ((size_t)(t * NB + n) * 3) * PLANE + o;
    op[0] = n0; op[PLANE] = n1; op[2*PLANE] = n2;
}

// ---------------- launch ----------------
extern "C" void kernel_launch(void* const* d_in, const int* in_sizes, int n_in,
                              void* d_out, int out_size)
{
    const float* frames = (const float*)d_in[0];
    const float* depths = (const float*)d_in[1];
    const float* mvs    = (const float*)d_in[2];
    const float* jits   = (const float*)d_in[3];
    const float* w1 = (const float*)d_in[4];
    const float* b1 = (const float*)d_in[5];
    const float* w2 = (const float*)d_in[6];
    const float* b2 = (const float*)d_in[7];
    const float* w3 = (const float*)d_in[8];
    const float* b3 = (const float*)d_in[9];
    float* out = (float*)d_out;

    cudaFuncSetAttribute(conv3ep_kernel, cudaFuncAttributeMaxDynamicSharedMemorySize, C3_SMEM);

    dim3 cgrid(WF/32, HF/4, NB);
    dim3 c3grid(WF/16, HF/16, NB);
    dim3 c3blk(16, 16);
    int pgrid = (NB*PLANE + 255) / 256;

    prepack_kernel<<<25, 256>>>(w1, w2, w3);

    for (int s = 0; s < Tt; s++) {
        int t = Tt - 1 - s;
        pre_kernel<<<pgrid, 256>>>(frames + (size_t)t * NB * 3 * SRC,
                                   depths + (size_t)t * NB * SRC,
                                   jits + (size_t)t * NB * 2,
                                   (s == 0) ? 1 : 0);
        if (s > 0)
            warp_kernel<<<pgrid, 256>>>(mvs + (size_t)t * NB * SRC * 2);
        conv1_kernel<<<cgrid, 256>>>(b1);
        conv2_kernel<<<cgrid, 256>>>(b2);
        conv3ep_kernel<<<c3grid, c3blk, C3_SMEM>>>(b3, out, t);
    }
}

// round 6
// speedup vs baseline: 7.4241x; 1.0310x over previous
#include <cuda_runtime.h>
#include <cuda_bf16.h>
#include <math.h>
#include <stdint.h>

#define Tt 3
#define NB 2
#define HH 360
#define WW 640
#define FF 2
#define HF 720
#define WF 1280
#define PLANE (HF*WF)
#define SRC (HH*WW)

// ---------------- device-global scratch ----------------
__device__ float4 g_fb4[NB*PLANE];            // frame_bicubic, NHWC float4 (fp32)
__device__ float4 g_hw4[NB*PLANE];            // warped history, NHWC float4 (fp32)
__device__ float4 g_ha [NB*PLANE];            // persistent history state
__device__ __nv_bfloat16 g_x0[(size_t)NB*PLANE*8];   // CNN input NHWC bf16
__device__ __nv_bfloat16 g_h1[(size_t)NB*PLANE*64];  // conv1 out NHWC bf16
__device__ __nv_bfloat16 g_h2[(size_t)NB*PLANE*64];  // conv2 out NHWC bf16
__device__ uint4 g_w1f[5*4*32];               // conv1 A fragments [kc][mt][lane]
__device__ uint4 g_w2f[9*4*4*32];             // conv2 A fragments [tap][kt][mt][lane]
__device__ float g_w3p[9*2*64];               // conv3 weights [tap][oc][ic] fp32

// ---------------- helpers ----------------
__device__ __forceinline__ void cubw(float t, float w[4]) {
    const float a = -0.75f;
    float t2 = t*t, t3 = t2*t;
    w[0] = a*(t3 - 2.0f*t2 + t);
    w[1] = (a + 2.0f)*t3 - (a + 3.0f)*t2 + 1.0f;
    float s = 1.0f - t;
    w[2] = (a + 2.0f)*s*s*s - (a + 3.0f)*s*s + 1.0f;
    float u = 2.0f - t;
    w[3] = a*u*u*u - 5.0f*a*u*u + 8.0f*a*u - 4.0f*a;
}

__device__ __forceinline__ float depth_tx(float d) {
    float z = 10.0f / (100.0f - d * 99.9f);
    return (z - 0.1f) * (1.0f / 99.9f);
}

__device__ __forceinline__ uint32_t packbf(float lo, float hi) {
    __nv_bfloat162 h = __floats2bfloat162_rn(lo, hi);
    return *reinterpret_cast<uint32_t*>(&h);
}

__device__ __forceinline__ void mma_bf16(float c[4], uint32_t a0, uint32_t a1,
                                         uint32_t a2, uint32_t a3,
                                         uint32_t b0, uint32_t b1) {
    asm volatile(
        "mma.sync.aligned.m16n8k16.row.col.f32.bf16.bf16.f32 "
        "{%0,%1,%2,%3}, {%4,%5,%6,%7}, {%8,%9}, {%0,%1,%2,%3};\n"
        : "+f"(c[0]), "+f"(c[1]), "+f"(c[2]), "+f"(c[3])
        : "r"(a0), "r"(a1), "r"(a2), "r"(a3), "r"(b0), "r"(b1));
}

// ---------------- weight prepack into MMA A-fragment layouts ----------------
__global__ void prepack_kernel(const float* __restrict__ w1,
                               const float* __restrict__ w2,
                               const float* __restrict__ w3)
{
    int i = blockIdx.x * 256 + threadIdx.x;
    if (i < 4608) {
        // conv2: e = ((tap*4+kt)*4+mt)*32 + lane ; oc = mt*16 + gid
        int lane = i & 31;
        int mt = (i >> 5) & 3;
        int kt = (i >> 7) & 3, tap = i >> 9;
        int gid = lane >> 2, tig = lane & 3;
        int oc = mt*16 + gid;
        int k0 = kt*16 + 2*tig;
        uint4 v;
        v.x = packbf(w2[(oc*64 + k0)*9 + tap],       w2[(oc*64 + k0 + 1)*9 + tap]);
        v.y = packbf(w2[((oc+8)*64 + k0)*9 + tap],   w2[((oc+8)*64 + k0 + 1)*9 + tap]);
        v.z = packbf(w2[(oc*64 + k0 + 8)*9 + tap],   w2[(oc*64 + k0 + 9)*9 + tap]);
        v.w = packbf(w2[((oc+8)*64 + k0 + 8)*9 + tap], w2[((oc+8)*64 + k0 + 9)*9 + tap]);
        g_w2f[i] = v;
    } else if (i < 4608 + 640) {
        // conv1: K = 80 = 5 chunks of (2 taps x 8 ic); tap 9 is zero pad
        int f = i - 4608;
        int lane = f & 31;
        int mt = (f >> 5) & 3;
        int kc = f >> 7;
        int gid = lane >> 2, tig = lane & 3;
        int oc = mt*16 + gid;
        int ic = 2*tig;
        int tlo = 2*kc, thi = 2*kc + 1;
        uint4 v;
        v.x = packbf(w1[(oc*8 + ic)*9 + tlo],     w1[(oc*8 + ic + 1)*9 + tlo]);
        v.y = packbf(w1[((oc+8)*8 + ic)*9 + tlo], w1[((oc+8)*8 + ic + 1)*9 + tlo]);
        if (thi <= 8) {
            v.z = packbf(w1[(oc*8 + ic)*9 + thi],     w1[(oc*8 + ic + 1)*9 + thi]);
            v.w = packbf(w1[((oc+8)*8 + ic)*9 + thi], w1[((oc+8)*8 + ic + 1)*9 + thi]);
        } else { v.z = 0u; v.w = 0u; }
        g_w1f[f] = v;
    } else if (i < 4608 + 640 + 1152) {
        int j = i - 5248;
        int tap = j >> 7, rem = j & 127;
        int oc = rem >> 6, ic = rem & 63;
        g_w3p[j] = w3[(oc*64 + ic)*9 + tap];
    }
}

// ---------------- first step: frame_bicubic + frame_up (+history init) ----------------
__global__ void pre_kernel(const float* __restrict__ frame,
                           const float* __restrict__ depth,
                           const float* __restrict__ jit)
{
    int idx = blockIdx.x * blockDim.x + threadIdx.x;
    if (idx >= NB*PLANE) return;
    int x = idx % WF;
    int y = (idx / WF) % HF;
    int n = idx / PLANE;

    float jx = jit[n*2 + 0];
    float jy = jit[n*2 + 1];

    float gx = (2.0f*x + 1.0f) / (float)WF - 1.0f + 2.0f*(0.5f - jx) / (float)WW;
    float gy = (2.0f*y + 1.0f) / (float)HF - 1.0f + 2.0f*(0.5f - jy) / (float)HH;
    float ix = ((gx + 1.0f) * (float)WW - 1.0f) * 0.5f;
    float iy = ((gy + 1.0f) * (float)HH - 1.0f) * 0.5f;
    float x0 = floorf(ix), y0 = floorf(iy);
    float wx[4], wy[4];
    cubw(ix - x0, wx);
    cubw(iy - y0, wy);
    int xi[4], yi[4];
    #pragma unroll
    for (int i = 0; i < 4; i++) {
        xi[i] = min(max((int)x0 + i - 1, 0), WW - 1);
        yi[i] = min(max((int)y0 + i - 1, 0), HH - 1);
    }

    const float* fr = frame + n * 3 * SRC;
    const float* dp = depth + n * SRC;
    float a0 = 0.f, a1 = 0.f, a2 = 0.f, a3 = 0.f;
    #pragma unroll
    for (int i = 0; i < 4; i++) {
        int ro = yi[i] * WW;
        #pragma unroll
        for (int j = 0; j < 4; j++) {
            float wgt = wy[i] * wx[j];
            int off = ro + xi[j];
            a0 += wgt * fr[off];
            a1 += wgt * fr[SRC + off];
            a2 += wgt * fr[2*SRC + off];
            a3 += wgt * depth_tx(dp[off]);
        }
    }
    int o = y * WF + x;
    g_fb4[n * PLANE + o] = make_float4(a0, a1, a2, a3);
    g_hw4[n * PLANE + o] = make_float4(a0, a1, a2, a3);

    int jxi = (int)floorf(jx * (float)FF);
    int jyi = (int)floorf(jy * (float)FF);
    int ux = x - jxi, uy = y - jyi;
    float u0 = 0.f, u1 = 0.f, u2 = 0.f, u3 = 0.f;
    if (ux >= 0 && uy >= 0 && (ux % FF) == 0 && (uy % FF) == 0) {
        int off = (uy / FF) * WW + (ux / FF);
        u0 = fr[off]; u1 = fr[SRC + off]; u2 = fr[2*SRC + off];
        u3 = depth_tx(dp[off]);
    }
    __nv_bfloat162* x0p = (__nv_bfloat162*)(g_x0 + ((size_t)n * PLANE + o) * 8);
    x0p[0] = __floats2bfloat162_rn(u0, u1);
    x0p[1] = __floats2bfloat162_rn(u2, u3);
    x0p[2] = __floats2bfloat162_rn(a0, a1);
    x0p[3] = __floats2bfloat162_rn(a2, a3);
}

// ---------------- later steps: pre + history warp fused ----------------
__global__ void prewarp_kernel(const float* __restrict__ frame,
                               const float* __restrict__ depth,
                               const float* __restrict__ jit,
                               const float* __restrict__ mv)
{
    int idx = blockIdx.x * blockDim.x + threadIdx.x;
    if (idx >= NB*PLANE) return;
    int x = idx % WF;
    int y = (idx / WF) % HF;
    int n = idx / PLANE;

    float jx = jit[n*2 + 0];
    float jy = jit[n*2 + 1];

    // ---- frame_bicubic ----
    float gx = (2.0f*x + 1.0f) / (float)WF - 1.0f + 2.0f*(0.5f - jx) / (float)WW;
    float gy = (2.0f*y + 1.0f) / (float)HF - 1.0f + 2.0f*(0.5f - jy) / (float)HH;
    float ix = ((gx + 1.0f) * (float)WW - 1.0f) * 0.5f;
    float iy = ((gy + 1.0f) * (float)HH - 1.0f) * 0.5f;
    float x0f_ = floorf(ix), y0f_ = floorf(iy);
    float wx[4], wy[4];
    cubw(ix - x0f_, wx);
    cubw(iy - y0f_, wy);
    int xi[4], yi[4];
    #pragma unroll
    for (int i = 0; i < 4; i++) {
        xi[i] = min(max((int)x0f_ + i - 1, 0), WW - 1);
        yi[i] = min(max((int)y0f_ + i - 1, 0), HH - 1);
    }
    const float* fr = frame + n * 3 * SRC;
    const float* dp = depth + n * SRC;
    float a0 = 0.f, a1 = 0.f, a2 = 0.f, a3 = 0.f;
    #pragma unroll
    for (int i = 0; i < 4; i++) {
        int ro = yi[i] * WW;
        #pragma unroll
        for (int j = 0; j < 4; j++) {
            float wgt = wy[i] * wx[j];
            int off = ro + xi[j];
            a0 += wgt * fr[off];
            a1 += wgt * fr[SRC + off];
            a2 += wgt * fr[2*SRC + off];
            a3 += wgt * depth_tx(dp[off]);
        }
    }
    int o = y * WF + x;
    g_fb4[n * PLANE + o] = make_float4(a0, a1, a2, a3);

    // ---- frame_up ----
    int jxi = (int)floorf(jx * (float)FF);
    int jyi = (int)floorf(jy * (float)FF);
    int ux = x - jxi, uy = y - jyi;
    float u0 = 0.f, u1 = 0.f, u2 = 0.f, u3 = 0.f;
    if (ux >= 0 && uy >= 0 && (ux % FF) == 0 && (uy % FF) == 0) {
        int off = (uy / FF) * WW + (ux / FF);
        u0 = fr[off]; u1 = fr[SRC + off]; u2 = fr[2*SRC + off];
        u3 = depth_tx(dp[off]);
    }
    __nv_bfloat162* x0p = (__nv_bfloat162*)(g_x0 + ((size_t)n * PLANE + o) * 8);
    x0p[0] = __floats2bfloat162_rn(u0, u1);
    x0p[1] = __floats2bfloat162_rn(u2, u3);

    // ---- history warp ----
    float cx = fmaxf(((float)x + 0.5f) / (float)FF - 0.5f, 0.0f);
    float cy = fmaxf(((float)y + 0.5f) / (float)FF - 0.5f, 0.0f);
    float fx0 = floorf(cx), fy0 = floorf(cy);
    float tx = cx - fx0, ty = cy - fy0;
    int mx0 = min(max((int)fx0, 0), WW - 1);
    int mx1 = min((int)fx0 + 1, WW - 1);
    int my0 = min(max((int)fy0, 0), HH - 1);
    int my1 = min((int)fy0 + 1, HH - 1);

    const float* m = mv + (size_t)n * SRC * 2;
    int i00 = (my0 * WW + mx0) * 2, i01 = (my0 * WW + mx1) * 2;
    int i10 = (my1 * WW + mx0) * 2, i11 = (my1 * WW + mx1) * 2;
    float mvx = (m[i00] * (1.f - tx) + m[i01] * tx) * (1.f - ty)
              + (m[i10] * (1.f - tx) + m[i11] * tx) * ty;
    float mvy = (m[i00+1] * (1.f - tx) + m[i01+1] * tx) * (1.f - ty)
              + (m[i10+1] * (1.f - tx) + m[i11+1] * tx) * ty;

    float4 res;
    bool oob = (mvx > 1.0f) || (mvx < -1.0f) || (mvy > 1.0f) || (mvy < -1.0f);
    if (oob) {
        res = make_float4(a0, a1, a2, a3);
    } else {
        float ixf = ((mvx + 1.0f) * (float)WF - 1.0f) * 0.5f;
        float iyf = ((mvy + 1.0f) * (float)HF - 1.0f) * 0.5f;
        float wx2[4], wy2[4];
        float x0w = floorf(ixf), y0w = floorf(iyf);
        cubw(ixf - x0w, wx2);
        cubw(iyf - y0w, wy2);
        int xj[4], yj[4];
        #pragma unroll
        for (int i = 0; i < 4; i++) {
            xj[i] = min(max((int)x0w + i - 1, 0), WF - 1);
            yj[i] = min(max((int)y0w + i - 1, 0), HF - 1);
        }
        const float4* hp = g_ha + n * PLANE;
        float b0 = 0.f, b1 = 0.f, b2 = 0.f, b3 = 0.f;
        #pragma unroll
        for (int i = 0; i < 4; i++) {
            int ro = yj[i] * WF;
            #pragma unroll
            for (int j = 0; j < 4; j++) {
                float wgt = wy2[i] * wx2[j];
                float4 v = hp[ro + xj[j]];
                b0 += wgt * v.x; b1 += wgt * v.y; b2 += wgt * v.z; b3 += wgt * v.w;
            }
        }
        res = make_float4(b0, b1, b2, b3);
    }
    g_hw4[n * PLANE + o] = res;
    x0p[2] = __floats2bfloat162_rn(res.x, res.y);
    x0p[3] = __floats2bfloat162_rn(res.z, res.w);
}

// ================= conv1: 8 -> 64, ReLU, bf16 MMA (K=80 padded) =================
// tile 32x8, 8 warps: warp = output row, M=64 per warp (mt 0..3), N=32 (nt 0..3)
__global__ void __launch_bounds__(256, 2) conv1_kernel(const float* __restrict__ bias)
{
    __shared__ uint4 s_x0[340];   // [10 rows][34 cols] x 8ch bf16 = 16B/px

    const int tid = threadIdx.x;
    const int lane = tid & 31, ly = tid >> 5;
    const int gid = lane >> 2, tig = lane & 3;
    const int n = blockIdx.z;
    const int x0t = blockIdx.x * 32, y0t = blockIdx.y * 8;

    for (int i = tid; i < 340; i += 256) {
        int r = i / 34, c = i - r * 34;
        int gy = min(max(y0t - 1 + r, 0), HF - 1);
        int gx = min(max(x0t - 1 + c, 0), WF - 1);
        s_x0[i] = *(const uint4*)(g_x0 + ((size_t)n * PLANE + gy * WF + gx) * 8);
    }
    __syncthreads();

    float acc[4][4][4] = {};
    const uint32_t* sp = (const uint32_t*)s_x0;

    #pragma unroll
    for (int kc = 0; kc < 5; kc++) {
        int tlo = 2*kc, thi = 2*kc + 1;
        uint4 A[4];
        #pragma unroll
        for (int mt = 0; mt < 4; mt++)
            A[mt] = __ldg(&g_w1f[(kc*4 + mt)*32 + lane]);
        int blo = (ly + tlo/3)*34 + tlo%3 + gid;
        if (thi <= 8) {
            int bhi = (ly + thi/3)*34 + thi%3 + gid;
            #pragma unroll
            for (int nt = 0; nt < 4; nt++) {
                uint32_t b0 = sp[(blo + nt*8)*4 + tig];
                uint32_t b1 = sp[(bhi + nt*8)*4 + tig];
                #pragma unroll
                for (int mt = 0; mt < 4; mt++)
                    mma_bf16(acc[mt][nt], A[mt].x, A[mt].y, A[mt].z, A[mt].w, b0, b1);
            }
        } else {
            #pragma unroll
            for (int nt = 0; nt < 4; nt++) {
                uint32_t b0 = sp[(blo + nt*8)*4 + tig];
                #pragma unroll
                for (int mt = 0; mt < 4; mt++)
                    mma_bf16(acc[mt][nt], A[mt].x, A[mt].y, A[mt].z, A[mt].w, b0, 0u);
            }
        }
    }

    __nv_bfloat16* dst = g_h1 + ((size_t)n * PLANE + (y0t + ly) * WF + x0t) * 64;
    #pragma unroll
    for (int mt = 0; mt < 4; mt++) {
        int oc0 = mt*16 + gid, oc1 = oc0 + 8;
        float bv0 = __ldg(&bias[oc0]), bv1 = __ldg(&bias[oc1]);
        #pragma unroll
        for (int nt = 0; nt < 4; nt++) {
            int px = nt*8 + 2*tig;
            dst[(size_t)px*64 + oc0]     = __float2bfloat16_rn(fmaxf(acc[mt][nt][0] + bv0, 0.f));
            dst[(size_t)(px+1)*64 + oc0] = __float2bfloat16_rn(fmaxf(acc[mt][nt][1] + bv0, 0.f));
            dst[(size_t)px*64 + oc1]     = __float2bfloat16_rn(fmaxf(acc[mt][nt][2] + bv1, 0.f));
            dst[(size_t)(px+1)*64 + oc1] = __float2bfloat16_rn(fmaxf(acc[mt][nt][3] + bv1, 0.f));
        }
    }
}

// ================= conv2: 64 -> 64, ReLU, bf16 MMA =================
// tile 32x8, 8 warps: warp = output row, M=64 per warp (mt 0..3), N=32 (nt 0..3)
__global__ void __launch_bounds__(256, 2) conv2_kernel(const float* __restrict__ bias)
{
    __shared__ uint4 s_in[340*9];  // [px 10x34][64ch bf16 = 8 uint4, pad to 9]

    const int tid = threadIdx.x;
    const int lane = tid & 31, ly = tid >> 5;
    const int gid = lane >> 2, tig = lane & 3;
    const int n = blockIdx.z;
    const int x0t = blockIdx.x * 32, y0t = blockIdx.y * 8;

    for (int i = tid; i < 340; i += 256) {
        int r = i / 34, c = i - r * 34;
        int gy = min(max(y0t - 1 + r, 0), HF - 1);
        int gx = min(max(x0t - 1 + c, 0), WF - 1);
        const uint4* src = (const uint4*)(g_h1 + ((size_t)n * PLANE + gy * WF + gx) * 64);
        uint4* dst = s_in + i * 9;
        #pragma unroll
        for (int j = 0; j < 8; j++) dst[j] = src[j];
    }
    __syncthreads();

    float acc[4][4][4] = {};
    const uint32_t* s32 = (const uint32_t*)s_in;

    for (int tap = 0; tap < 9; tap++) {
        int prow = (ly + tap/3)*34 + tap%3 + gid;
        #pragma unroll
        for (int kt = 0; kt < 4; kt++) {
            uint4 A[4];
            #pragma unroll
            for (int mt = 0; mt < 4; mt++)
                A[mt] = __ldg(&g_w2f[((tap*4 + kt)*4 + mt)*32 + lane]);
            #pragma unroll
            for (int nt = 0; nt < 4; nt++) {
                int w = (prow + nt*8)*36 + kt*8 + tig;
                uint32_t b0 = s32[w];
                uint32_t b1 = s32[w + 4];
                #pragma unroll
                for (int mt = 0; mt < 4; mt++)
                    mma_bf16(acc[mt][nt], A[mt].x, A[mt].y, A[mt].z, A[mt].w, b0, b1);
            }
        }
    }

    __nv_bfloat16* dst = g_h2 + ((size_t)n * PLANE + (y0t + ly) * WF + x0t) * 64;
    #pragma unroll
    for (int mt = 0; mt < 4; mt++) {
        int oc0 = mt*16 + gid, oc1 = oc0 + 8;
        float bv0 = __ldg(&bias[oc0]), bv1 = __ldg(&bias[oc1]);
        #pragma unroll
        for (int nt = 0; nt < 4; nt++) {
            int px = nt*8 + 2*tig;
            dst[(size_t)px*64 + oc0]     = __float2bfloat16_rn(fmaxf(acc[mt][nt][0] + bv0, 0.f));
            dst[(size_t)(px+1)*64 + oc0] = __float2bfloat16_rn(fmaxf(acc[mt][nt][1] + bv0, 0.f));
            dst[(size_t)px*64 + oc1]     = __float2bfloat16_rn(fmaxf(acc[mt][nt][2] + bv1, 0.f));
            dst[(size_t)(px+1)*64 + oc1] = __float2bfloat16_rn(fmaxf(acc[mt][nt][3] + bv1, 0.f));
        }
    }
}

// ================= conv3 (64->2) + blend/clamp epilogue =================
#define C3_SMEM (324*9*16 + 1152*4)

__global__ void __launch_bounds__(256) conv3ep_kernel(const float* __restrict__ bias,
                                                      float* __restrict__ out, int t)
{
    extern __shared__ char cm[];
    uint4* s_h2 = (uint4*)cm;                       // [18x18 px][8 uint4 pad 9]
    float* s_w3 = (float*)(cm + 324*9*16);          // [tap][oc][ic]

    const int tid = threadIdx.y * 16 + threadIdx.x;
    const int n = blockIdx.z;
    const int x0t = blockIdx.x * 16, y0t = blockIdx.y * 16;

    for (int i = tid; i < 1152; i += 256) s_w3[i] = g_w3p[i];
    for (int i = tid; i < 324; i += 256) {
        int r = i / 18, c = i - r * 18;
        int gy = min(max(y0t - 1 + r, 0), HF - 1);
        int gx = min(max(x0t - 1 + c, 0), WF - 1);
        const uint4* src = (const uint4*)(g_h2 + ((size_t)n * PLANE + gy * WF + gx) * 64);
        uint4* dst = s_h2 + i * 9;
        #pragma unroll
        for (int j = 0; j < 8; j++) dst[j] = src[j];
    }
    __syncthreads();

    float r0 = __ldg(&bias[0]);
    float r1 = __ldg(&bias[1]);

    #pragma unroll
    for (int tap = 0; tap < 9; tap++) {
        int p = (threadIdx.y + tap/3) * 18 + threadIdx.x + tap%3;
        const uint4* pp = s_h2 + p * 9;
        const float* wa = s_w3 + tap * 128;
        const float* wb = wa + 64;
        #pragma unroll
        for (int q = 0; q < 8; q++) {
            uint4 v = pp[q];
            float2 f0 = __bfloat1622float2(*(__nv_bfloat162*)&v.x);
            float2 f1 = __bfloat1622float2(*(__nv_bfloat162*)&v.y);
            float2 f2 = __bfloat1622float2(*(__nv_bfloat162*)&v.z);
            float2 f3 = __bfloat1622float2(*(__nv_bfloat162*)&v.w);
            int k = q * 8;
            r0 += f0.x*wa[k]   + f0.y*wa[k+1] + f1.x*wa[k+2] + f1.y*wa[k+3]
                + f2.x*wa[k+4] + f2.y*wa[k+5] + f3.x*wa[k+6] + f3.y*wa[k+7];
            r1 += f0.x*wb[k]   + f0.y*wb[k+1] + f1.x*wb[k+2] + f1.y*wb[k+3]
                + f2.x*wb[k+4] + f2.y*wb[k+5] + f3.x*wb[k+6] + f3.y*wb[k+7];
        }
    }

    int x = x0t + threadIdx.x;
    int y = y0t + threadIdx.y;
    int o = y * WF + x;
    float alpha = fminf(fmaxf(r0, 0.0f), 1.0f);
    float4 h = g_hw4[n * PLANE + o];
    float4 f = g_fb4[n * PLANE + o];
    float ia = 1.0f - alpha;
    float n0 = fminf(fmaxf(h.x * ia + f.x * alpha, 0.f), 1.f);
    float n1 = fminf(fmaxf(h.y * ia + f.y * alpha, 0.f), 1.f);
    float n2 = fminf(fmaxf(h.z * ia + f.z * alpha, 0.f), 1.f);
    float n3 = fminf(fmaxf(h.w * ia + f.w * alpha + r1, 0.f), 1.f);

    g_ha[n * PLANE + o] = make_float4(n0, n1, n2, n3);
    float* op = out + ((size_t)(t * NB + n) * 3) * PLANE + o;
    op[0] = n0; op[PLANE] = n1; op[2*PLANE] = n2;
}

// ---------------- launch ----------------
extern "C" void kernel_launch(void* const* d_in, const int* in_sizes, int n_in,
                              void* d_out, int out_size)
{
    const float* frames = (const float*)d_in[0];
    const float* depths = (const float*)d_in[1];
    const float* mvs    = (const float*)d_in[2];
    const float* jits   = (const float*)d_in[3];
    const float* w1 = (const float*)d_in[4];
    const float* b1 = (const float*)d_in[5];
    const float* w2 = (const float*)d_in[6];
    const float* b2 = (const float*)d_in[7];
    const float* w3 = (const float*)d_in[8];
    const float* b3 = (const float*)d_in[9];
    float* out = (float*)d_out;

    cudaFuncSetAttribute(conv3ep_kernel, cudaFuncAttributeMaxDynamicSharedMemorySize, C3_SMEM);

    dim3 cgrid(WF/32, HF/8, NB);
    dim3 c3grid(WF/16, HF/16, NB);
    dim3 c3blk(16, 16);
    int pgrid = (NB*PLANE + 255) / 256;

    prepack_kernel<<<25, 256>>>(w1, w2, w3);

    for (int s = 0; s < Tt; s++) {
        int t = Tt - 1 - s;
        if (s == 0) {
            pre_kernel<<<pgrid, 256>>>(frames + (size_t)t * NB * 3 * SRC,
                                       depths + (size_t)t * NB * SRC,
                                       jits + (size_t)t * NB * 2);
        } else {
            prewarp_kernel<<<pgrid, 256>>>(frames + (size_t)t * NB * 3 * SRC,
                                           depths + (size_t)t * NB * SRC,
                                           jits + (size_t)t * NB * 2,
                                           mvs + (size_t)t * NB * SRC * 2);
        }
        conv1_kernel<<<cgrid, 256>>>(b1);
        conv2_kernel<<<cgrid, 256>>>(b2);
        conv3ep_kernel<<<c3grid, c3blk, C3_SMEM>>>(b3, out, t);
    }
}